// round 7
// baseline (speedup 1.0000x reference)
#include <cuda_runtime.h>
#include <cuda_fp16.h>
#include <cstdint>

// VoxelGrid trilinear: fp16 8-corner pack (16B/cell, 32MB L2-resident),
// ONE LDG.128 gather per point, 8 points/thread for deep MLP, alpha output
// zeroed by a dedicated streaming kernel (query writes sigma only).
//
// Inputs: d_in[0]=x float32[N,3], d_in[1]=grid float32[200,200,50,1]
// Output: out[0:N]=sigma, out[N:2N]=alpha(=0)

#define SX 200
#define SY 200
#define SZ 50
#define NCELLS (SX * SY * SZ)     // 2,000,000
#define STRIDE_X (SY * SZ)        // 10000
#define STRIDE_Y (SZ)             // 50

__device__ uint4 g_packed_h[NCELLS];   // 32 MB static scratch

__device__ __forceinline__ unsigned int pack_h2(float lo, float hi)
{
    __half2 h = __floats2half2_rn(lo, hi);
    return *reinterpret_cast<unsigned int*>(&h);
}

__global__ __launch_bounds__(256)
void pack_kernel(const float* __restrict__ g)
{
    const int idx = blockIdx.x * blockDim.x + threadIdx.x;
    if (idx >= NCELLS) return;
    const int z = idx % SZ;
    const int y = (idx / SZ) % SY;
    const int x = idx / (SZ * SY);
    const int z1 = min(z + 1, SZ - 1);
    const int y1 = min(y + 1, SY - 1);
    const int x1 = min(x + 1, SX - 1);

    const float* b0 = g + x  * STRIDE_X;
    const float* b1 = g + x1 * STRIDE_X;

    uint4 c;
    c.x = pack_h2(__ldg(b0 + y  * STRIDE_Y + z), __ldg(b0 + y  * STRIDE_Y + z1));
    c.y = pack_h2(__ldg(b0 + y1 * STRIDE_Y + z), __ldg(b0 + y1 * STRIDE_Y + z1));
    c.z = pack_h2(__ldg(b1 + y  * STRIDE_Y + z), __ldg(b1 + y  * STRIDE_Y + z1));
    c.w = pack_h2(__ldg(b1 + y1 * STRIDE_Y + z), __ldg(b1 + y1 * STRIDE_Y + z1));
    g_packed_h[idx] = c;
}

// Zero the alpha half of the output with streaming float4 stores.
__global__ __launch_bounds__(256)
void zero_alpha_kernel(float* __restrict__ alpha, int n)
{
    const int t = blockIdx.x * blockDim.x + threadIdx.x;
    const long long i = (long long)t * 4;
    if (i >= n) return;
    __stcs(reinterpret_cast<float4*>(alpha + i),
           make_float4(0.0f, 0.0f, 0.0f, 0.0f));
}

__global__ __launch_bounds__(256)
void voxelgrid_kernel(const float* __restrict__ x,
                      float* __restrict__ out,
                      int n)
{
    const int t = blockIdx.x * blockDim.x + threadIdx.x;
    const long long base = (long long)t * 8;
    if (base >= n) return;

    // 8 points = 24 contiguous floats via 6 streaming float4 loads.
    const float4* xv = reinterpret_cast<const float4*>(x + base * 3);
    float4 v[6];
    #pragma unroll
    for (int i = 0; i < 6; ++i) v[i] = __ldcs(xv + i);
    const float* f = reinterpret_cast<const float*>(v);

    // Phase 1: compute cell index + weights, ISSUE ALL 8 GATHERS first.
    uint4 q[8];
    float wx[8], wy0_[8], wz0_[8], wy1_[8], wz1_[8];
    bool vld[8];

    #pragma unroll
    for (int p = 0; p < 8; ++p) {
        const float ix = (f[p * 3 + 0] + 4.0f) * 25.0f;
        const float iy = (f[p * 3 + 1] + 4.0f) * 25.0f;
        const float iz = (f[p * 3 + 2] + 1.0f) * 25.0f;

        vld[p] = (ix >= 0.0f) & (ix <= (float)(SX - 1)) &
                 (iy >= 0.0f) & (iy <= (float)(SY - 1)) &
                 (iz >= 0.0f) & (iz <= (float)(SZ - 1));

        const float fx = floorf(ix);
        const float fy = floorf(iy);
        const float fz = floorf(iz);

        const int x0 = min(max((int)fx, 0), SX - 1);
        const int y0 = min(max((int)fy, 0), SY - 1);
        const int z0 = min(max((int)fz, 0), SZ - 1);

        wx[p]  = ix - fx;
        const float ty = iy - fy;
        const float tz = iz - fz;
        wy1_[p] = ty;  wy0_[p] = 1.0f - ty;
        wz1_[p] = tz;  wz0_[p] = 1.0f - tz;

        q[p] = __ldg(&g_packed_h[x0 * STRIDE_X + y0 * STRIDE_Y + z0]);
    }

    // Phase 2: consume.
    float sig[8];
    #pragma unroll
    for (int p = 0; p < 8; ++p) {
        const float2 c00 = __half22float2(*reinterpret_cast<const __half2*>(&q[p].x));
        const float2 c01 = __half22float2(*reinterpret_cast<const __half2*>(&q[p].y));
        const float2 c10 = __half22float2(*reinterpret_cast<const __half2*>(&q[p].z));
        const float2 c11 = __half22float2(*reinterpret_cast<const __half2*>(&q[p].w));

        const float w00 = wy0_[p] * wz0_[p];
        const float w01 = wy0_[p] * wz1_[p];
        const float w10 = wy1_[p] * wz0_[p];
        const float w11 = wy1_[p] * wz1_[p];

        float inner0 = c00.x * w00;
        inner0 = fmaf(c00.y, w01, inner0);
        inner0 = fmaf(c01.x, w10, inner0);
        inner0 = fmaf(c01.y, w11, inner0);

        float inner1 = c10.x * w00;
        inner1 = fmaf(c10.y, w01, inner1);
        inner1 = fmaf(c11.x, w10, inner1);
        inner1 = fmaf(c11.y, w11, inner1);

        const float acc = fmaf(1.0f - wx[p], inner0, wx[p] * inner1);
        sig[p] = vld[p] ? acc : 0.0f;
    }

    float4* so = reinterpret_cast<float4*>(out + base);
    __stcs(so + 0, make_float4(sig[0], sig[1], sig[2], sig[3]));
    __stcs(so + 1, make_float4(sig[4], sig[5], sig[6], sig[7]));
}

extern "C" void kernel_launch(void* const* d_in, const int* in_sizes, int n_in,
                              void* d_out, int out_size)
{
    const float* x    = (const float*)d_in[0];
    const float* grid = (const float*)d_in[1];
    float* out = (float*)d_out;

    const int n = in_sizes[0] / 3;

    const int pack_threads = 256;
    const int pack_blocks = (NCELLS + pack_threads - 1) / pack_threads;
    pack_kernel<<<pack_blocks, pack_threads>>>(grid);

    const int zthreads = 256;
    const int zblocks = (n / 4 + zthreads - 1) / zthreads;
    zero_alpha_kernel<<<zblocks, zthreads>>>(out + n, n);

    const int threads = 256;
    const int pts_per_thread = 8;
    const int blocks = (n + threads * pts_per_thread - 1) / (threads * pts_per_thread);
    voxelgrid_kernel<<<blocks, threads>>>(x, out, n);
}

// round 8
// speedup vs baseline: 1.0604x; 1.0604x over previous
#include <cuda_runtime.h>
#include <cuda_fp16.h>
#include <cstdint>

// VoxelGrid trilinear: fp16 8-corner pack (16B/cell, 32MB -> L2-resident),
// ONE LDG.128 gather per point, 4 points/thread with explicit two-phase
// gather batching (issue all 4, then consume). Fused sigma+alpha stores.
//
// Inputs: d_in[0]=x float32[N,3], d_in[1]=grid float32[200,200,50,1]
// Output: out[0:N]=sigma, out[N:2N]=alpha(=0)

#define SX 200
#define SY 200
#define SZ 50
#define NCELLS (SX * SY * SZ)     // 2,000,000
#define STRIDE_X (SY * SZ)        // 10000
#define STRIDE_Y (SZ)             // 50

__device__ uint4 g_packed_h[NCELLS];   // 32 MB static scratch

__device__ __forceinline__ unsigned int pack_h2(float lo, float hi)
{
    __half2 h = __floats2half2_rn(lo, hi);
    return *reinterpret_cast<unsigned int*>(&h);
}

// grid: (SY*SX) blocks in .x is fine; use 2D decode to avoid div/mod by 50.
// blockIdx.x in [0, SX*SY), 64 threads cover z in [0,50) + headroom.
__global__ __launch_bounds__(64)
void pack_kernel(const float* __restrict__ g)
{
    const int z = threadIdx.x;
    if (z >= SZ) return;
    const int xy = blockIdx.x;
    const int y = xy % SY;
    const int x = xy / SY;

    const int z1 = min(z + 1, SZ - 1);
    const int y1 = min(y + 1, SY - 1);
    const int x1 = min(x + 1, SX - 1);

    const float* b0 = g + x  * STRIDE_X;
    const float* b1 = g + x1 * STRIDE_X;

    uint4 c;
    c.x = pack_h2(__ldg(b0 + y  * STRIDE_Y + z), __ldg(b0 + y  * STRIDE_Y + z1));
    c.y = pack_h2(__ldg(b0 + y1 * STRIDE_Y + z), __ldg(b0 + y1 * STRIDE_Y + z1));
    c.z = pack_h2(__ldg(b1 + y  * STRIDE_Y + z), __ldg(b1 + y  * STRIDE_Y + z1));
    c.w = pack_h2(__ldg(b1 + y1 * STRIDE_Y + z), __ldg(b1 + y1 * STRIDE_Y + z1));
    g_packed_h[xy * SZ + z] = c;
}

__global__ __launch_bounds__(256)
void voxelgrid_kernel(const float* __restrict__ x,
                      float* __restrict__ out,
                      int n)
{
    const int t = blockIdx.x * blockDim.x + threadIdx.x;
    const long long base = (long long)t * 4;
    if (base >= n) return;

    // 4 points = 12 contiguous floats, streaming loads (evict-first).
    const float4* xv = reinterpret_cast<const float4*>(x + base * 3);
    const float4 va = __ldcs(xv + 0);
    const float4 vb = __ldcs(xv + 1);
    const float4 vc = __ldcs(xv + 2);

    const float px[4] = {va.x, va.w, vb.z, vc.y};
    const float py[4] = {va.y, vb.x, vb.w, vc.z};
    const float pz[4] = {va.z, vb.y, vc.x, vc.w};

    // Phase 1: addresses + weights, issue ALL 4 gathers before consuming.
    uint4 q[4];
    float tx[4], ty[4], tz[4];
    bool vld[4];

    #pragma unroll
    for (int p = 0; p < 4; ++p) {
        const float ix = (px[p] + 4.0f) * 25.0f;
        const float iy = (py[p] + 4.0f) * 25.0f;
        const float iz = (pz[p] + 1.0f) * 25.0f;

        vld[p] = (ix >= 0.0f) & (ix <= (float)(SX - 1)) &
                 (iy >= 0.0f) & (iy <= (float)(SY - 1)) &
                 (iz >= 0.0f) & (iz <= (float)(SZ - 1));

        const int fx = __float2int_rd(ix);
        const int fy = __float2int_rd(iy);
        const int fz = __float2int_rd(iz);

        const int x0 = min(max(fx, 0), SX - 1);
        const int y0 = min(max(fy, 0), SY - 1);
        const int z0 = min(max(fz, 0), SZ - 1);

        tx[p] = ix - (float)fx;
        ty[p] = iy - (float)fy;
        tz[p] = iz - (float)fz;

        q[p] = __ldg(&g_packed_h[x0 * STRIDE_X + y0 * STRIDE_Y + z0]);
    }

    // Phase 2: consume.
    float sig[4];
    #pragma unroll
    for (int p = 0; p < 4; ++p) {
        const float2 c00 = __half22float2(*reinterpret_cast<const __half2*>(&q[p].x));
        const float2 c01 = __half22float2(*reinterpret_cast<const __half2*>(&q[p].y));
        const float2 c10 = __half22float2(*reinterpret_cast<const __half2*>(&q[p].z));
        const float2 c11 = __half22float2(*reinterpret_cast<const __half2*>(&q[p].w));

        const float sy0 = 1.0f - ty[p];
        const float sz0 = 1.0f - tz[p];
        const float w00 = sy0  * sz0;
        const float w01 = sy0  * tz[p];
        const float w10 = ty[p] * sz0;
        const float w11 = ty[p] * tz[p];

        float inner0 = c00.x * w00;
        inner0 = fmaf(c00.y, w01, inner0);
        inner0 = fmaf(c01.x, w10, inner0);
        inner0 = fmaf(c01.y, w11, inner0);

        float inner1 = c10.x * w00;
        inner1 = fmaf(c10.y, w01, inner1);
        inner1 = fmaf(c11.x, w10, inner1);
        inner1 = fmaf(c11.y, w11, inner1);

        const float acc = fmaf(1.0f - tx[p], inner0, tx[p] * inner1);
        sig[p] = vld[p] ? acc : 0.0f;
    }

    // Streaming stores: sigma then alpha(=0).
    float4* so = reinterpret_cast<float4*>(out + base);
    __stcs(so, make_float4(sig[0], sig[1], sig[2], sig[3]));
    float4* ao = reinterpret_cast<float4*>(out + (long long)n + base);
    __stcs(ao, make_float4(0.0f, 0.0f, 0.0f, 0.0f));
}

extern "C" void kernel_launch(void* const* d_in, const int* in_sizes, int n_in,
                              void* d_out, int out_size)
{
    const float* x    = (const float*)d_in[0];
    const float* grid = (const float*)d_in[1];
    float* out = (float*)d_out;

    const int n = in_sizes[0] / 3;

    pack_kernel<<<SX * SY, 64>>>(grid);

    const int threads = 256;
    const int pts_per_thread = 4;
    const int blocks = (n + threads * pts_per_thread - 1) / (threads * pts_per_thread);
    voxelgrid_kernel<<<blocks, threads>>>(x, out, n);
}

// round 9
// speedup vs baseline: 1.2207x; 1.1511x over previous
#include <cuda_runtime.h>
#include <cuda_fp16.h>
#include <cstdint>

// VoxelGrid trilinear: fp16 8-corner pack (16B/cell, 32MB -> L2-resident),
// ONE LDG.128 gather per point (R6 query structure, proven fastest).
// Pack kernel: 2 cells/thread with shared float2 row loads, PLUS fused
// alpha-zeroing blocks (query then writes sigma only).
//
// Inputs: d_in[0]=x float32[N,3], d_in[1]=grid float32[200,200,50,1]
// Output: out[0:N]=sigma, out[N:2N]=alpha(=0)

#define SX 200
#define SY 200
#define SZ 50
#define NCELLS (SX * SY * SZ)       // 2,000,000
#define STRIDE_X (SY * SZ)          // 10000
#define STRIDE_Y (SZ)               // 50

#define NPAIRS (NCELLS / 2)         // 1,000,000 (z-pairs)
#define PACK_THREADS 256
#define PACK_BLOCKS ((NPAIRS + PACK_THREADS - 1) / PACK_THREADS)   // 3907

__device__ uint4 g_packed_h[NCELLS];   // 32 MB static scratch

__device__ __forceinline__ unsigned int pack_h2(float lo, float hi)
{
    __half2 h = __floats2half2_rn(lo, hi);
    return *reinterpret_cast<unsigned int*>(&h);
}

// blocks [0, PACK_BLOCKS): pack 2 z-cells per thread.
// blocks [PACK_BLOCKS, ...): zero the alpha half of out (float4 streaming).
__global__ __launch_bounds__(PACK_THREADS)
void pack_and_zero_kernel(const float* __restrict__ g,
                          float* __restrict__ alpha, int n)
{
    if (blockIdx.x < PACK_BLOCKS) {
        const int i = blockIdx.x * PACK_THREADS + threadIdx.x;
        if (i >= NPAIRS) return;
        const int zi  = (i % (SZ / 2)) * 2;       // 0,2,...,48
        const int row = i / (SZ / 2);             // 0..39999
        const int y = row % SY;
        const int x = row / SY;
        const int y1 = min(y + 1, SY - 1);
        const int x1 = min(x + 1, SX - 1);
        const int zc = min(zi + 2, SZ - 1);       // clamped third corner

        const float* r00 = g + x  * STRIDE_X + y  * STRIDE_Y;
        const float* r01 = g + x  * STRIDE_X + y1 * STRIDE_Y;
        const float* r10 = g + x1 * STRIDE_X + y  * STRIDE_Y;
        const float* r11 = g + x1 * STRIDE_X + y1 * STRIDE_Y;

        // Row base is a multiple of 50 floats; zi even -> 8B-aligned float2.
        const float2 a00 = *reinterpret_cast<const float2*>(r00 + zi);
        const float2 a01 = *reinterpret_cast<const float2*>(r01 + zi);
        const float2 a10 = *reinterpret_cast<const float2*>(r10 + zi);
        const float2 a11 = *reinterpret_cast<const float2*>(r11 + zi);
        const float  c00 = r00[zc];
        const float  c01 = r01[zc];
        const float  c10 = r10[zc];
        const float  c11 = r11[zc];

        uint4 cell0, cell1;
        cell0.x = pack_h2(a00.x, a00.y);
        cell0.y = pack_h2(a01.x, a01.y);
        cell0.z = pack_h2(a10.x, a10.y);
        cell0.w = pack_h2(a11.x, a11.y);
        cell1.x = pack_h2(a00.y, c00);
        cell1.y = pack_h2(a01.y, c01);
        cell1.z = pack_h2(a10.y, c10);
        cell1.w = pack_h2(a11.y, c11);

        uint4* dst = &g_packed_h[row * STRIDE_Y + zi];
        dst[0] = cell0;
        dst[1] = cell1;
    } else {
        const int t = (blockIdx.x - PACK_BLOCKS) * PACK_THREADS + threadIdx.x;
        const long long idx = (long long)t * 4;
        if (idx >= n) return;
        __stcs(reinterpret_cast<float4*>(alpha + idx),
               make_float4(0.0f, 0.0f, 0.0f, 0.0f));
    }
}

__global__ __launch_bounds__(256)
void voxelgrid_kernel(const float* __restrict__ x,
                      float* __restrict__ out,
                      int n)
{
    const int t = blockIdx.x * blockDim.x + threadIdx.x;
    const long long base = (long long)t * 4;
    if (base >= n) return;

    // 4 points = 12 contiguous floats, streaming loads (evict-first).
    const float4* xv = reinterpret_cast<const float4*>(x + base * 3);
    const float4 va = __ldcs(xv + 0);
    const float4 vb = __ldcs(xv + 1);
    const float4 vc = __ldcs(xv + 2);

    const float px[4] = {va.x, va.w, vb.z, vc.y};
    const float py[4] = {va.y, vb.x, vb.w, vc.z};
    const float pz[4] = {va.z, vb.y, vc.x, vc.w};

    float sig[4];

    #pragma unroll
    for (int p = 0; p < 4; ++p) {
        const float ix = (px[p] + 4.0f) * 25.0f;
        const float iy = (py[p] + 4.0f) * 25.0f;
        const float iz = (pz[p] + 1.0f) * 25.0f;

        const bool valid =
            (ix >= 0.0f) & (ix <= (float)(SX - 1)) &
            (iy >= 0.0f) & (iy <= (float)(SY - 1)) &
            (iz >= 0.0f) & (iz <= (float)(SZ - 1));

        const float fx = floorf(ix);
        const float fy = floorf(iy);
        const float fz = floorf(iz);

        const int x0 = min(max((int)fx, 0), SX - 1);
        const int y0 = min(max((int)fy, 0), SY - 1);
        const int z0 = min(max((int)fz, 0), SZ - 1);

        const float tx = ix - fx;
        const float ty = iy - fy;
        const float tz = iz - fz;
        const float sy0 = 1.0f - ty, sz0 = 1.0f - tz;

        // Single 16B gather: all 8 corners (fp16).
        const uint4 q = __ldg(&g_packed_h[x0 * STRIDE_X + y0 * STRIDE_Y + z0]);
        const float2 c00 = __half22float2(*reinterpret_cast<const __half2*>(&q.x));
        const float2 c01 = __half22float2(*reinterpret_cast<const __half2*>(&q.y));
        const float2 c10 = __half22float2(*reinterpret_cast<const __half2*>(&q.z));
        const float2 c11 = __half22float2(*reinterpret_cast<const __half2*>(&q.w));

        const float w00 = sy0 * sz0;
        const float w01 = sy0 * tz;
        const float w10 = ty  * sz0;
        const float w11 = ty  * tz;

        float inner0 = c00.x * w00;
        inner0 = fmaf(c00.y, w01, inner0);
        inner0 = fmaf(c01.x, w10, inner0);
        inner0 = fmaf(c01.y, w11, inner0);

        float inner1 = c10.x * w00;
        inner1 = fmaf(c10.y, w01, inner1);
        inner1 = fmaf(c11.x, w10, inner1);
        inner1 = fmaf(c11.y, w11, inner1);

        const float acc = fmaf(1.0f - tx, inner0, tx * inner1);
        sig[p] = valid ? acc : 0.0f;
    }

    // Streaming sigma store only (alpha pre-zeroed by pack_and_zero_kernel).
    float4* so = reinterpret_cast<float4*>(out + base);
    __stcs(so, make_float4(sig[0], sig[1], sig[2], sig[3]));
}

extern "C" void kernel_launch(void* const* d_in, const int* in_sizes, int n_in,
                              void* d_out, int out_size)
{
    const float* x    = (const float*)d_in[0];
    const float* grid = (const float*)d_in[1];
    float* out = (float*)d_out;

    const int n = in_sizes[0] / 3;

    const int zero_blocks = (n / 4 + PACK_THREADS - 1) / PACK_THREADS;  // 8192
    pack_and_zero_kernel<<<PACK_BLOCKS + zero_blocks, PACK_THREADS>>>(grid, out + n, n);

    const int threads = 256;
    const int pts_per_thread = 4;
    const int blocks = (n + threads * pts_per_thread - 1) / (threads * pts_per_thread);
    voxelgrid_kernel<<<blocks, threads>>>(x, out, n);
}